// round 1
// baseline (speedup 1.0000x reference)
#include <cuda_runtime.h>
#include <math.h>

#define D_  64
#define H_  512
#define W_  512
#define NB  2
#define HW  (H_*W_)                 // 262144
#define NT  (NB*D_*H_*W_)           // 33554432
#define PAD 5
#define KS  11

// Scratch: 5 fields (x, y, xx, yy, xy), two ping-pong buffers.
__device__ float g_sA[5u * (unsigned)NT];
__device__ float g_sB[5u * (unsigned)NT];
__device__ double g_acc;

struct GW { float g[KS]; };

// ---------------------------------------------------------------------------
__global__ void k_zero_acc() { g_acc = 0.0; }

// ---------------------------------------------------------------------------
// Pass 1: blur along W (unit stride). Forms the 5 products from x,y on the fly.
__global__ void __launch_bounds__(256) k_pass_w(const float* __restrict__ x,
                                                const float* __restrict__ y,
                                                GW gw) {
    int idx = blockIdx.x * blockDim.x + threadIdx.x;
    if (idx >= NT) return;
    int w   = idx & (W_ - 1);
    int row = idx - w;

    float sx = 0.f, sy = 0.f, sxx = 0.f, syy = 0.f, sxy = 0.f;
#pragma unroll
    for (int t = 0; t < KS; t++) {
        int wi = w - PAD + t;
        wi = wi < 0 ? 0 : (wi > W_ - 1 ? W_ - 1 : wi);
        float xv = x[row + wi];
        float yv = y[row + wi];
        float g  = gw.g[t];
        sx  += g * xv;
        sy  += g * yv;
        sxx += g * xv * xv;
        syy += g * yv * yv;
        sxy += g * xv * yv;
    }
    g_sA[(size_t)idx]               = sx;
    g_sA[(size_t)NT + idx]          = sy;
    g_sA[2ull * NT + idx]           = sxx;
    g_sA[3ull * NT + idx]           = syy;
    g_sA[4ull * NT + idx]           = sxy;
}

// ---------------------------------------------------------------------------
// Pass 2: blur along H (stride W_). Coalesced along W; rows reused via L1/L2.
__global__ void __launch_bounds__(256) k_pass_h(GW gw) {
    int idx = blockIdx.x * blockDim.x + threadIdx.x;
    if (idx >= NT) return;
    int w    = idx & (W_ - 1);
    int h    = (idx >> 9) & (H_ - 1);
    int nd   = idx >> 18;           // n*D_ + d
    int base = nd << 18;            // nd * HW

    float acc0 = 0.f, acc1 = 0.f, acc2 = 0.f, acc3 = 0.f, acc4 = 0.f;
#pragma unroll
    for (int t = 0; t < KS; t++) {
        int hi = h - PAD + t;
        hi = hi < 0 ? 0 : (hi > H_ - 1 ? H_ - 1 : hi);
        int off = base + (hi << 9) + w;
        float g = gw.g[t];
        acc0 += g * g_sA[(size_t)off];
        acc1 += g * g_sA[(size_t)NT + off];
        acc2 += g * g_sA[2ull * NT + off];
        acc3 += g * g_sA[3ull * NT + off];
        acc4 += g * g_sA[4ull * NT + off];
    }
    g_sB[(size_t)idx]      = acc0;
    g_sB[(size_t)NT + idx] = acc1;
    g_sB[2ull * NT + idx]  = acc2;
    g_sB[3ull * NT + idx]  = acc3;
    g_sB[4ull * NT + idx]  = acc4;
}

// ---------------------------------------------------------------------------
// Pass 3: blur along D with a sliding register window (each element loaded
// exactly once), fused SSIM map + mean reduction.
__global__ void __launch_bounds__(256) k_pass_d(GW gw) {
    int col = blockIdx.x * blockDim.x + threadIdx.x;   // 0 .. NB*HW-1
    // col -> (n, h*w)
    int n    = col >> 18;           // / HW
    int hw   = col & (HW - 1);
    size_t base = (size_t)n * D_ * HW + hw;

    const float c1 = 0.01f * 0.01f;   // (K1*DATA_RANGE)^2
    const float c2 = 0.03f * 0.03f;   // (K2*DATA_RANGE)^2

    float win[5][KS];
    // init window: depths clamp(-5..5)
#pragma unroll
    for (int j = 0; j < KS; j++) {
        int dj = j - PAD;
        dj = dj < 0 ? 0 : (dj > D_ - 1 ? D_ - 1 : dj);
        size_t off = base + (size_t)dj * HW;
#pragma unroll
        for (int f = 0; f < 5; f++)
            win[f][j] = g_sB[(size_t)f * NT + off];
    }

    float lsum = 0.f;
    for (int d = 0; d < D_; d++) {
        float s0 = 0.f, s1 = 0.f, s2 = 0.f, s3 = 0.f, s4 = 0.f;
#pragma unroll
        for (int j = 0; j < KS; j++) {
            float g = gw.g[j];
            s0 += g * win[0][j];
            s1 += g * win[1][j];
            s2 += g * win[2][j];
            s3 += g * win[3][j];
            s4 += g * win[4][j];
        }
        // SSIM for this voxel
        float mu_x = s0, mu_y = s1;
        float mu_x2 = mu_x * mu_x;
        float mu_y2 = mu_y * mu_y;
        float mu_xy = mu_x * mu_y;
        float sig_x  = fmaxf(s2 - mu_x2, 0.f);
        float sig_y  = fmaxf(s3 - mu_y2, 0.f);
        float sig_xy = s4 - mu_xy;
        float num = (2.f * mu_xy + c1) * (2.f * sig_xy + c2);
        float den = (mu_x2 + mu_y2 + c1) * (sig_x + sig_y + c2);
        lsum += num / den;

        // shift window, load next depth
        int dn = d + PAD + 1;
        dn = dn > D_ - 1 ? D_ - 1 : dn;
        size_t off = base + (size_t)dn * HW;
#pragma unroll
        for (int j = 0; j < KS - 1; j++) {
#pragma unroll
            for (int f = 0; f < 5; f++)
                win[f][j] = win[f][j + 1];
        }
#pragma unroll
        for (int f = 0; f < 5; f++)
            win[f][KS - 1] = g_sB[(size_t)f * NT + off];
    }

    // block reduction
    unsigned lane = threadIdx.x & 31;
    unsigned wid  = threadIdx.x >> 5;
#pragma unroll
    for (int o = 16; o > 0; o >>= 1)
        lsum += __shfl_xor_sync(0xffffffffu, lsum, o);
    __shared__ float ws[8];
    if (lane == 0) ws[wid] = lsum;
    __syncthreads();
    if (wid == 0) {
        float v = lane < (blockDim.x >> 5) ? ws[lane] : 0.f;
#pragma unroll
        for (int o = 4; o > 0; o >>= 1)
            v += __shfl_xor_sync(0xffffffffu, v, o);
        if (lane == 0) atomicAdd(&g_acc, (double)v);
    }
}

// ---------------------------------------------------------------------------
__global__ void k_finalize(float* __restrict__ out, int n) {
    double mean = g_acc / (double)NT;
    for (int i = threadIdx.x; i < n; i += blockDim.x)
        out[i] = (float)mean;
}

// ---------------------------------------------------------------------------
extern "C" void kernel_launch(void* const* d_in, const int* in_sizes, int n_in,
                              void* d_out, int out_size) {
    const float* x = (const float*)d_in[0];
    const float* y = (const float*)d_in[1];
    float* out = (float*)d_out;

    // Gaussian weights (deterministic, computed every call, passed by value)
    GW gw;
    {
        double g[KS], s = 0.0;
        for (int i = 0; i < KS; i++) {
            double c = (double)(i - KS / 2);
            g[i] = exp(-(c * c) / (2.0 * 1.5 * 1.5));
            s += g[i];
        }
        for (int i = 0; i < KS; i++) gw.g[i] = (float)(g[i] / s);
    }

    k_zero_acc<<<1, 1>>>();
    k_pass_w<<<NT / 256, 256>>>(x, y, gw);
    k_pass_h<<<NT / 256, 256>>>(gw);
    k_pass_d<<<(NB * HW) / 256, 256>>>(gw);
    k_finalize<<<1, 32>>>(out, out_size);
}

// round 3
// speedup vs baseline: 1.1877x; 1.1877x over previous
#include <cuda_runtime.h>
#include <math.h>

#define D_  64
#define H_  512
#define W_  512
#define NB  2
#define HW  (H_*W_)                 // 262144
#define NT  (NB*D_*H_*W_)           // 33554432
#define PAD 5
#define KS  11
#define CH  64                      // H rows per block in fused WH kernel

// Scratch: 5 fields (x, y, xx, yy, xy) after W+H blur.
__device__ float g_sB[5u * (unsigned)NT];
__device__ double g_acc;

struct GW { float g[KS]; };

// ---------------------------------------------------------------------------
__global__ void k_zero_acc() { g_acc = 0.0; }

// ---------------------------------------------------------------------------
// Fused W+H blur. One block = one 64-row strip of one (n,d) slice, 512 threads
// (one per w). Per input row: stage x,y in smem (double buffered), W-blur the
// 5 product fields in registers, scatter-accumulate into 11 pending H outputs
// held in registers (unroll-by-11 => all slot indices static).
//
// Slot protocol: output h lives in slot (h-h0) mod 11. At iteration j, the
// k=10 term is the FIRST contribution of new output h0+j (weight g[0], slot
// u=j%11) and is an ASSIGNMENT — this both starts the new output and kills the
// stale tenant (fixes the warm-up corruption of the first 11 rows per strip).
__global__ void __launch_bounds__(512, 1) k_wh(const float* __restrict__ x,
                                               const float* __restrict__ y,
                                               GW gw) {
    __shared__ float xs[2][W_], ys[2][W_];
    int b  = blockIdx.x;
    int hc = b & 7;                 // H_/CH = 8 strips
    int nd = b >> 3;                // n*D_ + d
    int h0 = hc << 6;               // * CH
    size_t slice = (size_t)nd * HW;
    int w = threadIdx.x;

    const float* xsl = x + slice;
    const float* ysl = y + slice;

    float acc[5][11];
#pragma unroll
    for (int f = 0; f < 5; f++)
#pragma unroll
        for (int s = 0; s < 11; s++) acc[f][s] = 0.f;

    // Input rows r = h0-5 .. h0+CH+4  (j = 0..73), padded to 77 for unroll.
#pragma unroll 1
    for (int jb = 0; jb < 77; jb += 11) {
#pragma unroll
        for (int u = 0; u < 11; u++) {
            int j = jb + u;
            if (j < CH + 10) {
                int r  = h0 - PAD + j;
                int rr = r < 0 ? 0 : (r > H_ - 1 ? H_ - 1 : r);
                int buf = j & 1;
                xs[buf][w] = xsl[(size_t)rr * W_ + w];
                ys[buf][w] = ysl[(size_t)rr * W_ + w];
                __syncthreads();

                float sx = 0.f, sy = 0.f, sxx = 0.f, syy = 0.f, sxy = 0.f;
#pragma unroll
                for (int t = 0; t < KS; t++) {
                    int wi = w - PAD + t;
                    wi = wi < 0 ? 0 : (wi > W_ - 1 ? W_ - 1 : wi);
                    float xv = xs[buf][wi];
                    float yv = ys[buf][wi];
                    float g  = gw.g[t];
                    sx  += g * xv;
                    sy  += g * yv;
                    sxx += g * xv * xv;
                    syy += g * yv * yv;
                    sxy += g * xv * yv;
                }

                // Row r contributes to outputs h = r-5+k with weight g[10-k];
                // slot(h) = (u + k + 1) mod 11 (static).
#pragma unroll
                for (int k = 0; k < 10; k++) {
                    int s = (u + k + 1) % 11;
                    float gk = gw.g[10 - k];
                    acc[0][s] += gk * sx;
                    acc[1][s] += gk * sy;
                    acc[2][s] += gk * sxx;
                    acc[3][s] += gk * syy;
                    acc[4][s] += gk * sxy;
                }
                // k = 10: first contribution of output h0+j -> ASSIGN slot u.
                {
                    float gk = gw.g[0];
                    acc[0][u] = gk * sx;
                    acc[1][u] = gk * sy;
                    acc[2][u] = gk * sxx;
                    acc[3][u] = gk * syy;
                    acc[4][u] = gk * sxy;
                }

                // Output h = h0+j-10 completes at this row (slot (u+1)%11).
                if (j >= 10) {
                    int h = h0 + j - 10;
                    int s = (u + 1) % 11;
                    size_t o = slice + (size_t)h * W_ + w;
                    g_sB[o]              = acc[0][s];
                    g_sB[(size_t)NT + o] = acc[1][s];
                    g_sB[2ull*NT + o]    = acc[2][s];
                    g_sB[3ull*NT + o]    = acc[3][s];
                    g_sB[4ull*NT + o]    = acc[4][s];
                    // no reset needed: slot restarted later via k=10 assignment
                }
            }
        }
    }
}

// ---------------------------------------------------------------------------
// D-pass: rotating register window (no shifts — slots static via unroll-by-11),
// fused SSIM map + mean reduction. Each element loaded exactly once.
__global__ void __launch_bounds__(256) k_pass_d(GW gw) {
    int col = blockIdx.x * blockDim.x + threadIdx.x;   // 0 .. NB*HW-1
    int n   = col >> 18;            // / HW
    int hw  = col & (HW - 1);
    size_t base = (size_t)n * D_ * HW + hw;

    const float c1 = 0.01f * 0.01f;
    const float c2 = 0.03f * 0.03f;

    // At iteration d, window element k (depth d-5+k) lives in slot (d+k)%11.
    float win[5][KS];
#pragma unroll
    for (int k = 0; k < KS; k++) {
        int dj = k - PAD;
        dj = dj < 0 ? 0 : dj;                 // upper clamp impossible here
        size_t off = base + (size_t)dj * HW;
#pragma unroll
        for (int f = 0; f < 5; f++)
            win[f][k] = g_sB[(size_t)f * NT + off];
    }

    float lsum = 0.f;
#pragma unroll 1
    for (int dbase = 0; dbase < 66; dbase += 11) {
#pragma unroll
        for (int u = 0; u < 11; u++) {
            int d = dbase + u;
            float s0 = 0.f, s1 = 0.f, s2 = 0.f, s3 = 0.f, s4 = 0.f;
#pragma unroll
            for (int k = 0; k < KS; k++) {
                float g = gw.g[k];
                int s = (u + k) % 11;          // static
                s0 += g * win[0][s];
                s1 += g * win[1][s];
                s2 += g * win[2][s];
                s3 += g * win[3][s];
                s4 += g * win[4][s];
            }
            float mu_x = s0, mu_y = s1;
            float mu_x2 = mu_x * mu_x;
            float mu_y2 = mu_y * mu_y;
            float mu_xy = mu_x * mu_y;
            float sig_x  = fmaxf(s2 - mu_x2, 0.f);
            float sig_y  = fmaxf(s3 - mu_y2, 0.f);
            float sig_xy = s4 - mu_xy;
            float num = (2.f * mu_xy + c1) * (2.f * sig_xy + c2);
            float den = (mu_x2 + mu_y2 + c1) * (sig_x + sig_y + c2);
            if (d < D_) lsum += num / den;

            // Replace oldest (depth d-5, slot d%11 == u) with depth d+6.
            int dn = d + PAD + 1;
            dn = dn > D_ - 1 ? D_ - 1 : dn;
            size_t off = base + (size_t)dn * HW;
#pragma unroll
            for (int f = 0; f < 5; f++)
                win[f][u] = g_sB[(size_t)f * NT + off];
        }
    }

    // block reduction
    unsigned lane = threadIdx.x & 31;
    unsigned wid  = threadIdx.x >> 5;
#pragma unroll
    for (int o = 16; o > 0; o >>= 1)
        lsum += __shfl_xor_sync(0xffffffffu, lsum, o);
    __shared__ float ws[8];
    if (lane == 0) ws[wid] = lsum;
    __syncthreads();
    if (wid == 0) {
        float v = lane < (blockDim.x >> 5) ? ws[lane] : 0.f;
#pragma unroll
        for (int o = 4; o > 0; o >>= 1)
            v += __shfl_xor_sync(0xffffffffu, v, o);
        if (lane == 0) atomicAdd(&g_acc, (double)v);
    }
}

// ---------------------------------------------------------------------------
__global__ void k_finalize(float* __restrict__ out, int n) {
    double mean = g_acc / (double)NT;
    for (int i = threadIdx.x; i < n; i += blockDim.x)
        out[i] = (float)mean;
}

// ---------------------------------------------------------------------------
extern "C" void kernel_launch(void* const* d_in, const int* in_sizes, int n_in,
                              void* d_out, int out_size) {
    const float* x = (const float*)d_in[0];
    const float* y = (const float*)d_in[1];
    float* out = (float*)d_out;

    GW gw;
    {
        double g[KS], s = 0.0;
        for (int i = 0; i < KS; i++) {
            double c = (double)(i - KS / 2);
            g[i] = exp(-(c * c) / (2.0 * 1.5 * 1.5));
            s += g[i];
        }
        for (int i = 0; i < KS; i++) gw.g[i] = (float)(g[i] / s);
    }

    k_zero_acc<<<1, 1>>>();
    k_wh<<<NB * D_ * (H_ / CH), 512>>>(x, y, gw);
    k_pass_d<<<(NB * HW) / 256, 256>>>(gw);
    k_finalize<<<1, 32>>>(out, out_size);
}

// round 4
// speedup vs baseline: 1.6355x; 1.3771x over previous
#include <cuda_runtime.h>
#include <math.h>

#define D_  64
#define H_  512
#define W_  512
#define NB  2
#define HW  (H_*W_)                 // 262144
#define NT  (NB*D_*H_*W_)           // 33554432
#define PAD 5
#define KS  11
#define CH  64                      // H rows per block in fused WH kernel

typedef unsigned long long u64;

// Scratch: 5 fields (x, y, xx, yy, xy) after W+H blur.
__device__ float g_sB[5u * (unsigned)NT];
__device__ double g_acc;

struct GW { float g[KS]; };

// ---- packed f32x2 helpers ---------------------------------------------------
__device__ __forceinline__ u64 pk2(float lo, float hi) {
    u64 r; asm("mov.b64 %0, {%1, %2};" : "=l"(r) : "f"(lo), "f"(hi)); return r;
}
__device__ __forceinline__ void upk2(u64 v, float& lo, float& hi) {
    asm("mov.b64 {%0, %1}, %2;" : "=f"(lo), "=f"(hi) : "l"(v));
}
__device__ __forceinline__ u64 fma2(u64 a, u64 b, u64 c) {
    u64 d; asm("fma.rn.f32x2 %0, %1, %2, %3;" : "=l"(d) : "l"(a), "l"(b), "l"(c));
    return d;
}
__device__ __forceinline__ u64 mul2(u64 a, u64 b) {
    u64 d; asm("mul.rn.f32x2 %0, %1, %2;" : "=l"(d) : "l"(a), "l"(b));
    return d;
}

// ---------------------------------------------------------------------------
__global__ void k_zero_acc() { g_acc = 0.0; }

// ---------------------------------------------------------------------------
// Fused W+H blur. One block = one 64-row strip of one (n,d) slice, 512 threads
// (one per w). Per input row: prefetch next row into registers (hides DRAM
// latency under compute), stage current row in smem (double buffered), W-blur
// the 5 product fields with packed f32x2 math, scatter-accumulate into 11
// pending H outputs held in packed registers (unroll-by-11 => static slots).
//
// Slot protocol: output h lives in slot (h-h0) mod 11. At iteration j, the
// k=10 term is the FIRST contribution of new output h0+j (weight g[0], slot
// u=j%11) and is an ASSIGNMENT (kills the stale tenant).
__global__ void __launch_bounds__(512, 1) k_wh(const float* __restrict__ x,
                                               const float* __restrict__ y,
                                               GW gw) {
    __shared__ float xs[2][W_], ys[2][W_];
    int b  = blockIdx.x;
    int hc = b & 7;                 // H_/CH = 8 strips
    int nd = b >> 3;                // n*D_ + d
    int h0 = hc << 6;               // * CH
    size_t slice = (size_t)nd * HW;
    int w = threadIdx.x;

    const float* xsl = x + slice;
    const float* ysl = y + slice;

    u64 gg[KS];
#pragma unroll
    for (int t = 0; t < KS; t++) gg[t] = pk2(gw.g[t], gw.g[t]);

    u64 acc01[11], acc23[11];
    float acc4[11];
#pragma unroll
    for (int s = 0; s < 11; s++) { acc01[s] = 0; acc23[s] = 0; acc4[s] = 0.f; }

    // Prefetch row j=0.
    float px, py;
    {
        int r = h0 - PAD;
        int rr = r < 0 ? 0 : r;
        px = xsl[(size_t)rr * W_ + w];
        py = ysl[(size_t)rr * W_ + w];
    }

    // Input rows r = h0-5 .. h0+CH+4  (j = 0..73), padded to 77 for unroll.
#pragma unroll 1
    for (int jb = 0; jb < 77; jb += 11) {
#pragma unroll
        for (int u = 0; u < 11; u++) {
            int j = jb + u;
            if (j < CH + 10) {
                int buf = j & 1;
                xs[buf][w] = px;
                ys[buf][w] = py;
                __syncthreads();

                // Prefetch row j+1 (overlaps with compute below).
                {
                    int r = h0 - PAD + j + 1;
                    int rr = r < 0 ? 0 : (r > H_ - 1 ? H_ - 1 : r);
                    px = xsl[(size_t)rr * W_ + w];
                    py = ysl[(size_t)rr * W_ + w];
                }

                // W-blur of the 5 product fields (packed: (sx,sy),(sxx,syy)).
                u64 s01 = 0, s23 = 0;
                float s4 = 0.f;
#pragma unroll
                for (int t = 0; t < KS; t++) {
                    int wi = w - PAD + t;
                    wi = wi < 0 ? 0 : (wi > W_ - 1 ? W_ - 1 : wi);
                    float xv = xs[buf][wi];
                    float yv = ys[buf][wi];
                    u64 p  = pk2(xv, yv);
                    s01 = fma2(gg[t], p, s01);
                    u64 pp = mul2(p, p);
                    s23 = fma2(gg[t], pp, s23);
                    s4  = fmaf(gw.g[t] * xv, yv, s4);
                }

                // Row r contributes to outputs h = r-5+k with weight g[10-k];
                // slot(h) = (u + k + 1) mod 11 (static).
#pragma unroll
                for (int k = 0; k < 10; k++) {
                    int s = (u + k + 1) % 11;
                    acc01[s] = fma2(gg[10 - k], s01, acc01[s]);
                    acc23[s] = fma2(gg[10 - k], s23, acc23[s]);
                    acc4[s]  = fmaf(gw.g[10 - k], s4, acc4[s]);
                }
                // k = 10: first contribution of output h0+j -> ASSIGN slot u.
                acc01[u] = mul2(gg[0], s01);
                acc23[u] = mul2(gg[0], s23);
                acc4[u]  = gw.g[0] * s4;

                // Output h = h0+j-10 completes at this row (slot (u+1)%11).
                if (j >= 10) {
                    int h = h0 + j - 10;
                    int s = (u + 1) % 11;
                    size_t o = slice + (size_t)h * W_ + w;
                    float a0, a1, a2, a3;
                    upk2(acc01[s], a0, a1);
                    upk2(acc23[s], a2, a3);
                    g_sB[o]              = a0;
                    g_sB[(size_t)NT + o] = a1;
                    g_sB[2ull*NT + o]    = a2;
                    g_sB[3ull*NT + o]    = a3;
                    g_sB[4ull*NT + o]    = acc4[s];
                }
            }
        }
    }
}

// ---------------------------------------------------------------------------
// D-pass: rotating register window (no shifts — slots static via unroll-by-11),
// fused SSIM map + mean reduction. Each element loaded exactly once.
__global__ void __launch_bounds__(256) k_pass_d(GW gw) {
    int col = blockIdx.x * blockDim.x + threadIdx.x;   // 0 .. NB*HW-1
    int n   = col >> 18;            // / HW
    int hw  = col & (HW - 1);
    size_t base = (size_t)n * D_ * HW + hw;

    const float c1 = 0.01f * 0.01f;
    const float c2 = 0.03f * 0.03f;

    // At iteration d, window element k (depth d-5+k) lives in slot (d+k)%11.
    float win[5][KS];
#pragma unroll
    for (int k = 0; k < KS; k++) {
        int dj = k - PAD;
        dj = dj < 0 ? 0 : dj;
        size_t off = base + (size_t)dj * HW;
#pragma unroll
        for (int f = 0; f < 5; f++)
            win[f][k] = g_sB[(size_t)f * NT + off];
    }

    float lsum = 0.f;
#pragma unroll 1
    for (int dbase = 0; dbase < 66; dbase += 11) {
#pragma unroll
        for (int u = 0; u < 11; u++) {
            int d = dbase + u;
            float s0 = 0.f, s1 = 0.f, s2 = 0.f, s3 = 0.f, s4 = 0.f;
#pragma unroll
            for (int k = 0; k < KS; k++) {
                float g = gw.g[k];
                int s = (u + k) % 11;          // static
                s0 += g * win[0][s];
                s1 += g * win[1][s];
                s2 += g * win[2][s];
                s3 += g * win[3][s];
                s4 += g * win[4][s];
            }
            float mu_x = s0, mu_y = s1;
            float mu_x2 = mu_x * mu_x;
            float mu_y2 = mu_y * mu_y;
            float mu_xy = mu_x * mu_y;
            float sig_x  = fmaxf(s2 - mu_x2, 0.f);
            float sig_y  = fmaxf(s3 - mu_y2, 0.f);
            float sig_xy = s4 - mu_xy;
            float num = (2.f * mu_xy + c1) * (2.f * sig_xy + c2);
            float den = (mu_x2 + mu_y2 + c1) * (sig_x + sig_y + c2);
            if (d < D_) lsum += num / den;

            // Replace oldest (depth d-5, slot d%11 == u) with depth d+6.
            int dn = d + PAD + 1;
            dn = dn > D_ - 1 ? D_ - 1 : dn;
            size_t off = base + (size_t)dn * HW;
#pragma unroll
            for (int f = 0; f < 5; f++)
                win[f][u] = g_sB[(size_t)f * NT + off];
        }
    }

    // block reduction
    unsigned lane = threadIdx.x & 31;
    unsigned wid  = threadIdx.x >> 5;
#pragma unroll
    for (int o = 16; o > 0; o >>= 1)
        lsum += __shfl_xor_sync(0xffffffffu, lsum, o);
    __shared__ float ws[8];
    if (lane == 0) ws[wid] = lsum;
    __syncthreads();
    if (wid == 0) {
        float v = lane < (blockDim.x >> 5) ? ws[lane] : 0.f;
#pragma unroll
        for (int o = 4; o > 0; o >>= 1)
            v += __shfl_xor_sync(0xffffffffu, v, o);
        if (lane == 0) atomicAdd(&g_acc, (double)v);
    }
}

// ---------------------------------------------------------------------------
__global__ void k_finalize(float* __restrict__ out, int n) {
    double mean = g_acc / (double)NT;
    for (int i = threadIdx.x; i < n; i += blockDim.x)
        out[i] = (float)mean;
}

// ---------------------------------------------------------------------------
extern "C" void kernel_launch(void* const* d_in, const int* in_sizes, int n_in,
                              void* d_out, int out_size) {
    const float* x = (const float*)d_in[0];
    const float* y = (const float*)d_in[1];
    float* out = (float*)d_out;

    GW gw;
    {
        double g[KS], s = 0.0;
        for (int i = 0; i < KS; i++) {
            double c = (double)(i - KS / 2);
            g[i] = exp(-(c * c) / (2.0 * 1.5 * 1.5));
            s += g[i];
        }
        for (int i = 0; i < KS; i++) gw.g[i] = (float)(g[i] / s);
    }

    k_zero_acc<<<1, 1>>>();
    k_wh<<<NB * D_ * (H_ / CH), 512>>>(x, y, gw);
    k_pass_d<<<(NB * HW) / 256, 256>>>(gw);
    k_finalize<<<1, 32>>>(out, out_size);
}